// round 9
// baseline (speedup 1.0000x reference)
#include <cuda_runtime.h>
#include <stdint.h>

// Problem constants
#define BATCH   32
#define NATOM   256
#define NN      100
#define NFEAT   42
#define H       50
#define NATOMS  (BATCH * NATOM)          // 8192
#define DF_PER_ATOM (NN * NFEAT * 3)     // 12600
#define DE_PAD  48                       // padded dE row (12 float4)

// Scratch: per-atom input gradient dE/dx, rows padded to 48 floats (1.57 MB)
__device__ float g_dE[NATOMS * DE_PAD];

// Fast accurate tanh: 1 - 2/(e^{2x}+1). ~1e-7 rel err, saturates correctly.
__device__ __forceinline__ float tanh_fast(float x) {
    float e = __expf(2.0f * x);
    return 1.0f - __fdividef(2.0f, e + 1.0f);
}

#define W0P 51   // padded row stride for W0s (42 x 51)
#define W1P 51   // padded row stride for W1s (50 x 51)
#define APW 4    // atoms per warp

// ---------------------------------------------------------------------------
// Kernel A: per-atom MLP forward + input gradient. FOUR atoms per warp:
// weight LDS amortized 4x, 8 independent FMA chains for latency hiding.
// Block = 256 threads = 8 warps = 32 consecutive atoms (type-pure: 32 | 128).
// ---------------------------------------------------------------------------
__global__ __launch_bounds__(256) void fc_kernel(
    const float* __restrict__ image,
    const float* __restrict__ W0t0, const float* __restrict__ b0t0,
    const float* __restrict__ W1t0, const float* __restrict__ b1t0,
    const float* __restrict__ W2t0, const float* __restrict__ b2t0,
    const float* __restrict__ W0t1, const float* __restrict__ b0t1,
    const float* __restrict__ W1t1, const float* __restrict__ b1t1,
    const float* __restrict__ W2t1, const float* __restrict__ b2t1,
    float* __restrict__ Ei_out)
{
    __shared__ float W0s[NFEAT * W0P];   // padded rows: [f][i]
    __shared__ float W1s[H * W1P];       // padded rows: [i][j]
    __shared__ float W2s[H], b0s[H], b1s[H];
    __shared__ float b2s;
    __shared__ float xs[32][NFEAT];      // per-block atoms' inputs
    __shared__ float h0s[32][H];
    __shared__ float g1s[32][H];
    __shared__ float g0s[32][H];

    const int tid = threadIdx.x;
    const int w   = tid >> 5;
    const int l   = tid & 31;
    const int atom0 = blockIdx.x * 32 + w * APW;   // this warp's first atom
    const int wa    = w * APW;                     // shared row base
    // whole block is one type (32 divides 128)
    const int type = ((blockIdx.x * 32) & (NATOM - 1)) >= 128 ? 1 : 0;

    const float* W0 = type ? W0t1 : W0t0;
    const float* B0 = type ? b0t1 : b0t0;
    const float* W1 = type ? W1t1 : W1t0;
    const float* B1 = type ? b1t1 : b1t0;
    const float* W2 = type ? W2t1 : W2t0;
    const float* B2 = type ? b2t1 : b2t0;

    for (int i = tid; i < NFEAT * H; i += 256) W0s[(i / H) * W0P + (i % H)] = W0[i];
    for (int i = tid; i < H * H;     i += 256) W1s[(i / H) * W1P + (i % H)] = W1[i];
    if (tid < H) { W2s[tid] = W2[tid]; b0s[tid] = B0[tid]; b1s[tid] = B1[tid]; }
    if (tid == 0) b2s = B2[0];

    // load x: 4*42 = 168 contiguous floats per warp
    {
        const float* xg = image + (size_t)atom0 * NFEAT;
        for (int i = l; i < APW * NFEAT; i += 32)
            xs[wa + i / NFEAT][i % NFEAT] = xg[i];
    }
    __syncthreads();

    const bool hi = (l < H - 32);   // l < 18 handles output index l+32

    // ---- layer 0: h0 = tanh(x @ W0 + b0) ----
    float h0A[APW], h0B[APW];
    #pragma unroll
    for (int a = 0; a < APW; ++a) { h0A[a] = b0s[l]; h0B[a] = hi ? b0s[l + 32] : 0.f; }
    #pragma unroll
    for (int f = 0; f < NFEAT; ++f) {
        float wlo = W0s[f * W0P + l];
        float whi = hi ? W0s[f * W0P + l + 32] : 0.f;
        #pragma unroll
        for (int a = 0; a < APW; ++a) {
            float xv = xs[wa + a][f];
            h0A[a] = fmaf(wlo, xv, h0A[a]);
            h0B[a] = fmaf(whi, xv, h0B[a]);
        }
    }
    #pragma unroll
    for (int a = 0; a < APW; ++a) {
        h0A[a] = tanh_fast(h0A[a]);
        h0s[wa + a][l] = h0A[a];
        if (hi) { h0B[a] = tanh_fast(h0B[a]); h0s[wa + a][l + 32] = h0B[a]; }
    }
    __syncwarp();

    // ---- layer 1: h1 = tanh(h0 @ W1 + b1) ----
    float h1A[APW], h1B[APW];
    #pragma unroll
    for (int a = 0; a < APW; ++a) { h1A[a] = b1s[l]; h1B[a] = hi ? b1s[l + 32] : 0.f; }
    #pragma unroll
    for (int i = 0; i < H; ++i) {
        float wlo = W1s[i * W1P + l];
        float whi = hi ? W1s[i * W1P + l + 32] : 0.f;
        #pragma unroll
        for (int a = 0; a < APW; ++a) {
            float hv = h0s[wa + a][i];
            h1A[a] = fmaf(wlo, hv, h1A[a]);
            h1B[a] = fmaf(whi, hv, h1B[a]);
        }
    }
    #pragma unroll
    for (int a = 0; a < APW; ++a) {
        h1A[a] = tanh_fast(h1A[a]);
        if (hi) h1B[a] = tanh_fast(h1B[a]);
    }

    // ---- Ei = h1 @ W2 + b2 ----
    #pragma unroll
    for (int a = 0; a < APW; ++a) {
        float p = h1A[a] * W2s[l] + (hi ? h1B[a] * W2s[l + 32] : 0.f);
        #pragma unroll
        for (int off = 16; off > 0; off >>= 1)
            p += __shfl_down_sync(0xFFFFFFFFu, p, off);
        if (l == 0) Ei_out[atom0 + a] = p + b2s;
    }

    // ---- backward: g1 = W2 * (1 - h1^2) ----
    #pragma unroll
    for (int a = 0; a < APW; ++a) {
        g1s[wa + a][l] = W2s[l] * (1.f - h1A[a] * h1A[a]);
        if (hi) g1s[wa + a][l + 32] = W2s[l + 32] * (1.f - h1B[a] * h1B[a]);
    }
    __syncwarp();

    // ---- g0[i] = (sum_j W1[i,j] * g1[j]) * (1 - h0[i]^2) ----
    float gA[APW], gB[APW];
    #pragma unroll
    for (int a = 0; a < APW; ++a) { gA[a] = 0.f; gB[a] = 0.f; }
    #pragma unroll
    for (int j = 0; j < H; ++j) {
        float wlo = W1s[l * W1P + j];
        float whi = hi ? W1s[(l + 32) * W1P + j] : 0.f;
        #pragma unroll
        for (int a = 0; a < APW; ++a) {
            float gv = g1s[wa + a][j];
            gA[a] = fmaf(wlo, gv, gA[a]);
            gB[a] = fmaf(whi, gv, gB[a]);
        }
    }
    #pragma unroll
    for (int a = 0; a < APW; ++a) {
        gA[a] *= (1.f - h0A[a] * h0A[a]);
        g0s[wa + a][l] = gA[a];
        if (hi) { gB[a] *= (1.f - h0B[a] * h0B[a]); g0s[wa + a][l + 32] = gB[a]; }
    }
    __syncwarp();

    // ---- dx[f] = sum_i W0[f,i] * g0[i] ----  (f = l and l+32 for l<10)
    const bool lo2 = (l < NFEAT - 32);  // l < 10
    float dA[APW], dB[APW];
    #pragma unroll
    for (int a = 0; a < APW; ++a) { dA[a] = 0.f; dB[a] = 0.f; }
    #pragma unroll
    for (int i = 0; i < H; ++i) {
        float wlo = W0s[l * W0P + i];
        float whi = lo2 ? W0s[(l + 32) * W0P + i] : 0.f;
        #pragma unroll
        for (int a = 0; a < APW; ++a) {
            float gv = g0s[wa + a][i];
            dA[a] = fmaf(wlo, gv, dA[a]);
            dB[a] = fmaf(whi, gv, dB[a]);
        }
    }
    #pragma unroll
    for (int a = 0; a < APW; ++a) {
        float* dE = g_dE + (size_t)(atom0 + a) * DE_PAD;
        dE[l] = dA[a];
        if (lo2) dE[l + 32] = dB[a];
    }
}

// ---------------------------------------------------------------------------
// Kernel B: Etot[b] = sum_n Ei[b, n]. One block per batch.
// ---------------------------------------------------------------------------
__global__ __launch_bounds__(256) void etot_kernel(
    const float* __restrict__ Ei, float* __restrict__ Etot)
{
    __shared__ float s[256];
    int b = blockIdx.x, tid = threadIdx.x;
    s[tid] = Ei[b * NATOM + tid];
    __syncthreads();
    for (int off = 128; off > 0; off >>= 1) {
        if (tid < off) s[tid] += s[tid + off];
        __syncthreads();
    }
    if (tid == 0) Etot[b] = s[0];
}

// ---------------------------------------------------------------------------
// Kernel C: Force[b,n,d] = sum_{k,f} dE_pad[b, nbr[b,n,k], f] * dfeat[b,n,k,f,d]
// One block per (b,n). 128 threads.
//   Gather: 1200 float4 loads from padded g_dE rows.
//   Stream: LDG.128; 2 k-rows = 252 floats = 63 float4; thread tt owns float4
//   q=tt, so each element has loop-invariant (k_off, f, d). Threads 0-62 do
//   rows (kb,kb+1), threads 64-126 rows (kb+2,kb+3); kb += 4 (25 iters).
// ---------------------------------------------------------------------------
__global__ __launch_bounds__(128) void force_kernel(
    const float* __restrict__ dfeat,
    const int* __restrict__ neighbor,
    float* __restrict__ force)
{
    __shared__ int    nbr[NN];
    __shared__ float  dEs[NN * DE_PAD];   // 100 x 48 floats = 19.2 KB
    __shared__ float  red[3][128];

    const int tid  = threadIdx.x;
    const int atom = blockIdx.x;
    const int b    = atom >> 8;

    const int* nb = neighbor + (size_t)atom * NN;
    if (tid < NN) nbr[tid] = nb[tid];
    __syncthreads();

    // gather neighbor dE rows as float4 (12 per row); neighbor==0 -> zero row
    {
        const float4* gdE4 = (const float4*)g_dE;
        float4* dEs4 = (float4*)dEs;
        const float4 z4 = make_float4(0.f, 0.f, 0.f, 0.f);
        #pragma unroll
        for (int it = 0; it < 10; ++it) {           // 10*128 = 1280 >= 1200
            int idx = tid + it * 128;
            if (idx < NN * (DE_PAD / 4)) {
                int k = idx / (DE_PAD / 4);
                int q = idx - k * (DE_PAD / 4);
                int v = nbr[k];
                dEs4[idx] = v ? gdE4[(size_t)(b * NATOM + v - 1) * (DE_PAD / 4) + q] : z4;
            }
        }
    }
    __syncthreads();

    // per-thread loop-invariant element mapping within its 2-row chunk
    const int h  = tid >> 6;        // 0 or 1 -> which row pair
    const int tt = tid & 63;        // float4 slot within chunk
    const bool act = (tt < 63);

    int koff[4], ff[4];
    #pragma unroll
    for (int j = 0; j < 4; ++j) {
        int e = 4 * tt + j;             // element in [0, 252)
        koff[j] = e / 126;
        int r = e - 126 * koff[j];
        ff[j] = r / 3;
    }
    const int d0 = (4 * tt) % 3;        // d of elements j=0 and j=3

    const float4* df4 = (const float4*)(dfeat + (size_t)atom * DF_PER_ATOM);
    float acc0 = 0.f, acc1 = 0.f, acc2 = 0.f, acc3 = 0.f;
    if (act) {
        #pragma unroll 5
        for (int kb = 0; kb < NN; kb += 4) {
            int krow = kb + 2 * h;                       // even
            float4 v = __ldcs(df4 + (size_t)(krow >> 1) * 63 + tt);
            acc0 = fmaf(dEs[(krow + koff[0]) * DE_PAD + ff[0]], v.x, acc0);
            acc1 = fmaf(dEs[(krow + koff[1]) * DE_PAD + ff[1]], v.y, acc1);
            acc2 = fmaf(dEs[(krow + koff[2]) * DE_PAD + ff[2]], v.z, acc2);
            acc3 = fmaf(dEs[(krow + koff[3]) * DE_PAD + ff[3]], v.w, acc3);
        }
    }
    // deposit into per-d slots (d of j: d0, d0+1, d0+2, d0)
    if (act) {
        red[d0][tid]           = acc0 + acc3;
        red[(d0 + 1) % 3][tid] = acc1;
        red[(d0 + 2) % 3][tid] = acc2;
    } else {
        red[0][tid] = 0.f; red[1][tid] = 0.f; red[2][tid] = 0.f;
    }
    __syncthreads();

    if (tid < 96) {
        const int d = tid >> 5, ln = tid & 31;
        float s = red[d][ln] + red[d][ln + 32] + red[d][ln + 64] + red[d][ln + 96];
        #pragma unroll
        for (int off = 16; off > 0; off >>= 1)
            s += __shfl_down_sync(0xFFFFFFFFu, s, off);
        if (ln == 0) force[(size_t)atom * 3 + d] = s;
    }
}

// ---------------------------------------------------------------------------
// Launch. Output layout (fp32): [Etot(32) | Ei(8192) | Force(24576)] = 32800
// ---------------------------------------------------------------------------
extern "C" void kernel_launch(void* const* d_in, const int* in_sizes, int n_in,
                              void* d_out, int out_size)
{
    const float* image    = (const float*)d_in[0];
    const float* dfeat    = (const float*)d_in[1];
    const int*   neighbor = (const int*)d_in[2];
    const float *W0t0 = (const float*)d_in[3],  *b0t0 = (const float*)d_in[4];
    const float *W1t0 = (const float*)d_in[5],  *b1t0 = (const float*)d_in[6];
    const float *W2t0 = (const float*)d_in[7],  *b2t0 = (const float*)d_in[8];
    const float *W0t1 = (const float*)d_in[9],  *b0t1 = (const float*)d_in[10];
    const float *W1t1 = (const float*)d_in[11], *b1t1 = (const float*)d_in[12];
    const float *W2t1 = (const float*)d_in[13], *b2t1 = (const float*)d_in[14];

    float* out    = (float*)d_out;
    float* etot   = out;
    float* ei     = out + BATCH;
    float* forceo = out + BATCH + NATOMS;

    fc_kernel<<<NATOMS / 32, 256>>>(image,
        W0t0, b0t0, W1t0, b1t0, W2t0, b2t0,
        W0t1, b0t1, W1t1, b1t1, W2t1, b2t1,
        ei);
    etot_kernel<<<BATCH, 256>>>(ei, etot);
    force_kernel<<<NATOMS, 128>>>(dfeat, neighbor, forceo);
}

// round 11
// speedup vs baseline: 1.5262x; 1.5262x over previous
#include <cuda_runtime.h>
#include <stdint.h>

// Problem constants
#define BATCH   32
#define NATOM   256
#define NN      100
#define NFEAT   42
#define H       50
#define NATOMS  (BATCH * NATOM)          // 8192
#define DF_PER_ATOM (NN * NFEAT * 3)     // 12600
#define DE_PAD  48                       // padded dE row (12 float4)

// Scratch: per-atom input gradient dE/dx, rows padded to 48 floats (1.57 MB)
__device__ float g_dE[NATOMS * DE_PAD];

// Fast accurate tanh: 1 - 2/(e^{2x}+1). ~1e-7 rel err, saturates correctly.
__device__ __forceinline__ float tanh_fast(float x) {
    float e = __expf(2.0f * x);
    return 1.0f - __fdividef(2.0f, e + 1.0f);
}

#define W0P 51   // padded row stride for W0s (42 x 51)
#define W1P 51   // padded row stride for W1s (50 x 51)

// ---------------------------------------------------------------------------
// Kernel A (R8 version — known 28.2us): warp-per-atom MLP fwd + input grad.
// Block = 256 threads = 8 warps = 8 consecutive atoms (type-pure: 8 | 128).
// ---------------------------------------------------------------------------
__global__ __launch_bounds__(256) void fc_kernel(
    const float* __restrict__ image,
    const float* __restrict__ W0t0, const float* __restrict__ b0t0,
    const float* __restrict__ W1t0, const float* __restrict__ b1t0,
    const float* __restrict__ W2t0, const float* __restrict__ b2t0,
    const float* __restrict__ W0t1, const float* __restrict__ b0t1,
    const float* __restrict__ W1t1, const float* __restrict__ b1t1,
    const float* __restrict__ W2t1, const float* __restrict__ b2t1,
    float* __restrict__ Ei_out)
{
    __shared__ float W0s[NFEAT * W0P];   // padded rows: [f][i]
    __shared__ float W1s[H * W1P];       // padded rows: [i][j]
    __shared__ float W2s[H], b0s[H], b1s[H];
    __shared__ float b2s;
    __shared__ float xs[8][NFEAT];
    __shared__ float h0s[8][H];
    __shared__ float g1s[8][H];
    __shared__ float g0s[8][H];

    const int tid = threadIdx.x;
    const int w   = tid >> 5;
    const int l   = tid & 31;
    const int atom = blockIdx.x * 8 + w;
    const int n = atom & (NATOM - 1);
    const int type = (n >= 128) ? 1 : 0;

    const float* W0 = type ? W0t1 : W0t0;
    const float* B0 = type ? b0t1 : b0t0;
    const float* W1 = type ? W1t1 : W1t0;
    const float* B1 = type ? b1t1 : b1t0;
    const float* W2 = type ? W2t1 : W2t0;
    const float* B2 = type ? b2t1 : b2t0;

    for (int i = tid; i < NFEAT * H; i += 256) W0s[(i / H) * W0P + (i % H)] = W0[i];
    for (int i = tid; i < H * H;     i += 256) W1s[(i / H) * W1P + (i % H)] = W1[i];
    if (tid < H) { W2s[tid] = W2[tid]; b0s[tid] = B0[tid]; b1s[tid] = B1[tid]; }
    if (tid == 0) b2s = B2[0];
    __syncthreads();

    const float* xg = image + (size_t)atom * NFEAT;
    for (int f = l; f < NFEAT; f += 32) xs[w][f] = xg[f];
    __syncwarp();

    const bool hi = (l < H - 32);   // l < 18

    // ---- layer 0 ----
    float h0a = b0s[l];
    float h0b = hi ? b0s[l + 32] : 0.f;
    #pragma unroll
    for (int f = 0; f < NFEAT; ++f) {
        float xv = xs[w][f];
        h0a = fmaf(W0s[f * W0P + l], xv, h0a);
        if (hi) h0b = fmaf(W0s[f * W0P + l + 32], xv, h0b);
    }
    h0a = tanh_fast(h0a);
    if (hi) h0b = tanh_fast(h0b);
    h0s[w][l] = h0a;
    if (hi) h0s[w][l + 32] = h0b;
    __syncwarp();

    // ---- layer 1 ----
    float h1a = b1s[l];
    float h1b = hi ? b1s[l + 32] : 0.f;
    #pragma unroll
    for (int i = 0; i < H; ++i) {
        float hv = h0s[w][i];
        h1a = fmaf(W1s[i * W1P + l], hv, h1a);
        if (hi) h1b = fmaf(W1s[i * W1P + l + 32], hv, h1b);
    }
    h1a = tanh_fast(h1a);
    if (hi) h1b = tanh_fast(h1b);

    // ---- Ei ----
    float p = h1a * W2s[l] + (hi ? h1b * W2s[l + 32] : 0.f);
    #pragma unroll
    for (int off = 16; off > 0; off >>= 1)
        p += __shfl_down_sync(0xFFFFFFFFu, p, off);
    if (l == 0) Ei_out[atom] = p + b2s;

    // ---- backward ----
    g1s[w][l] = W2s[l] * (1.f - h1a * h1a);
    if (hi) g1s[w][l + 32] = W2s[l + 32] * (1.f - h1b * h1b);
    __syncwarp();

    float ga = 0.f, gb = 0.f;
    #pragma unroll
    for (int j = 0; j < H; ++j) {
        float gv = g1s[w][j];
        ga = fmaf(W1s[l * W1P + j], gv, ga);
        if (hi) gb = fmaf(W1s[(l + 32) * W1P + j], gv, gb);
    }
    ga *= (1.f - h0a * h0a);
    if (hi) gb *= (1.f - h0b * h0b);
    g0s[w][l] = ga;
    if (hi) g0s[w][l + 32] = gb;
    __syncwarp();

    float da = 0.f, db = 0.f;
    #pragma unroll
    for (int i = 0; i < H; ++i) {
        float gv = g0s[w][i];
        da = fmaf(W0s[l * W0P + i], gv, da);
        if (l < NFEAT - 32) db = fmaf(W0s[(l + 32) * W0P + i], gv, db);
    }
    float* dE = g_dE + (size_t)atom * DE_PAD;
    dE[l] = da;
    if (l < NFEAT - 32) dE[l + 32] = db;
}

// ---------------------------------------------------------------------------
// Kernel B: Etot[b] = sum_n Ei[b, n]. One block per batch.
// ---------------------------------------------------------------------------
__global__ __launch_bounds__(256) void etot_kernel(
    const float* __restrict__ Ei, float* __restrict__ Etot)
{
    __shared__ float s[256];
    int b = blockIdx.x, tid = threadIdx.x;
    s[tid] = Ei[b * NATOM + tid];
    __syncthreads();
    for (int off = 128; off > 0; off >>= 1) {
        if (tid < off) s[tid] += s[tid + off];
        __syncthreads();
    }
    if (tid == 0) Etot[b] = s[0];
}

// ---------------------------------------------------------------------------
// Kernel C: Force[b,n,d] = sum_{k,f} dE_pad[b, nbr[b,n,k], f] * dfeat[b,n,k,f,d]
// One block per (b,n). 256 threads = 4 groups of 64 (63 active).
//   Group g owns 2-row chunks starting at krow = kb + 2g; kb += 8 (13 iters).
//   Each active thread: 1 LDG.128 per iter with explicit next-iter prefetch
//   (>=1 outstanding DRAM load per thread throughout the stream).
// ---------------------------------------------------------------------------
__global__ __launch_bounds__(256) void force_kernel(
    const float* __restrict__ dfeat,
    const int* __restrict__ neighbor,
    float* __restrict__ force)
{
    __shared__ int    nbr[NN];
    __shared__ float  dEs[NN * DE_PAD];   // 100 x 48 floats = 19.2 KB
    __shared__ float  red[3][256];        // 3 KB

    const int tid  = threadIdx.x;
    const int atom = blockIdx.x;
    const int b    = atom >> 8;

    const int* nb = neighbor + (size_t)atom * NN;
    if (tid < NN) nbr[tid] = nb[tid];
    __syncthreads();

    // gather neighbor dE rows as float4 (12 per row); neighbor==0 -> zero row
    {
        const float4* gdE4 = (const float4*)g_dE;
        float4* dEs4 = (float4*)dEs;
        const float4 z4 = make_float4(0.f, 0.f, 0.f, 0.f);
        #pragma unroll
        for (int it = 0; it < 5; ++it) {            // 5*256 = 1280 >= 1200
            int idx = tid + it * 256;
            if (idx < NN * (DE_PAD / 4)) {
                int k = idx / (DE_PAD / 4);
                int q = idx - k * (DE_PAD / 4);
                int v = nbr[k];
                dEs4[idx] = v ? gdE4[(size_t)(b * NATOM + v - 1) * (DE_PAD / 4) + q] : z4;
            }
        }
    }
    __syncthreads();

    // loop-invariant element mapping: 2-row chunk = 252 floats = 63 float4
    const int g  = tid >> 6;        // group 0..3 -> row-pair offset 2g
    const int tt = tid & 63;        // float4 slot within chunk
    const bool act = (tt < 63);

    int koff[4], ff[4];
    #pragma unroll
    for (int j = 0; j < 4; ++j) {
        int e = 4 * tt + j;             // element in [0, 252)
        koff[j] = e / 126;
        int r = e - 126 * koff[j];
        ff[j] = r / 3;
    }
    const int d0 = (4 * tt) % 3;        // d of elements j=0 and j=3

    const float4* df4 = (const float4*)(dfeat + (size_t)atom * DF_PER_ATOM);
    float acc0 = 0.f, acc1 = 0.f, acc2 = 0.f, acc3 = 0.f;

    // software-pipelined stream: prefetch next chunk while consuming current
    float4 v = make_float4(0.f, 0.f, 0.f, 0.f);
    {
        int krow = 2 * g;
        if (act && krow < NN) v = __ldcs(df4 + (size_t)(krow >> 1) * 63 + tt);
    }
    #pragma unroll
    for (int kb = 0; kb < NN; kb += 8) {
        const int krow  = kb + 2 * g;
        const int krown = krow + 8;
        float4 vn = make_float4(0.f, 0.f, 0.f, 0.f);
        if (act && krown < NN) vn = __ldcs(df4 + (size_t)(krown >> 1) * 63 + tt);
        if (act && krow < NN) {
            acc0 = fmaf(dEs[(krow + koff[0]) * DE_PAD + ff[0]], v.x, acc0);
            acc1 = fmaf(dEs[(krow + koff[1]) * DE_PAD + ff[1]], v.y, acc1);
            acc2 = fmaf(dEs[(krow + koff[2]) * DE_PAD + ff[2]], v.z, acc2);
            acc3 = fmaf(dEs[(krow + koff[3]) * DE_PAD + ff[3]], v.w, acc3);
        }
        v = vn;
    }

    // deposit per-d partials (d of j: d0, d0+1, d0+2, d0)
    if (act) {
        red[d0][tid]           = acc0 + acc3;
        red[(d0 + 1) % 3][tid] = acc1;
        red[(d0 + 2) % 3][tid] = acc2;
    } else {
        red[0][tid] = 0.f; red[1][tid] = 0.f; red[2][tid] = 0.f;
    }
    __syncthreads();

    if (tid < 96) {
        const int d = tid >> 5, ln = tid & 31;
        float s = 0.f;
        #pragma unroll
        for (int c = 0; c < 256; c += 32) s += red[d][ln + c];
        #pragma unroll
        for (int off = 16; off > 0; off >>= 1)
            s += __shfl_down_sync(0xFFFFFFFFu, s, off);
        if (ln == 0) force[(size_t)atom * 3 + d] = s;
    }
}

// ---------------------------------------------------------------------------
// Launch. Output layout (fp32): [Etot(32) | Ei(8192) | Force(24576)] = 32800
// ---------------------------------------------------------------------------
extern "C" void kernel_launch(void* const* d_in, const int* in_sizes, int n_in,
                              void* d_out, int out_size)
{
    const float* image    = (const float*)d_in[0];
    const float* dfeat    = (const float*)d_in[1];
    const int*   neighbor = (const int*)d_in[2];
    const float *W0t0 = (const float*)d_in[3],  *b0t0 = (const float*)d_in[4];
    const float *W1t0 = (const float*)d_in[5],  *b1t0 = (const float*)d_in[6];
    const float *W2t0 = (const float*)d_in[7],  *b2t0 = (const float*)d_in[8];
    const float *W0t1 = (const float*)d_in[9],  *b0t1 = (const float*)d_in[10];
    const float *W1t1 = (const float*)d_in[11], *b1t1 = (const float*)d_in[12];
    const float *W2t1 = (const float*)d_in[13], *b2t1 = (const float*)d_in[14];

    float* out    = (float*)d_out;
    float* etot   = out;
    float* ei     = out + BATCH;
    float* forceo = out + BATCH + NATOMS;

    fc_kernel<<<NATOMS / 8, 256>>>(image,
        W0t0, b0t0, W1t0, b1t0, W2t0, b2t0,
        W0t1, b0t1, W1t1, b1t1, W2t1, b2t1,
        ei);
    etot_kernel<<<BATCH, 256>>>(ei, etot);
    force_kernel<<<NATOMS, 256>>>(dfeat, neighbor, forceo);
}

// round 13
// speedup vs baseline: 1.5965x; 1.0461x over previous
#include <cuda_runtime.h>
#include <stdint.h>

// Problem constants
#define BATCH   32
#define NATOM   256
#define NN      100
#define NFEAT   42
#define H       50
#define NATOMS  (BATCH * NATOM)          // 8192
#define DF_PER_ATOM (NN * NFEAT * 3)     // 12600
#define DE_PAD  48                       // padded dE row (12 float4)

// Scratch: per-atom input gradient dE/dx, rows padded to 48 floats (1.57 MB)
__device__ float g_dE[NATOMS * DE_PAD];

// Fast accurate tanh: 1 - 2/(e^{2x}+1). ~1e-7 rel err, saturates correctly.
__device__ __forceinline__ float tanh_fast(float x) {
    float e = __expf(2.0f * x);
    return 1.0f - __fdividef(2.0f, e + 1.0f);
}

#define W0P 51   // padded row stride for W0s (42 x 51)
#define W1P 51   // padded row stride for W1s (50 x 51)
#define APW 2    // atoms per warp
#define APB 16   // atoms per block (8 warps * 2)

// ---------------------------------------------------------------------------
// Kernel A: MLP fwd + input grad. TWO atoms per warp (weight LDS amortized 2x,
// 4 independent FMA chains), 16 atoms/block -> grid 512 (occupancy preserved).
// Type-pure blocks: 16 | 128.
// ---------------------------------------------------------------------------
__global__ __launch_bounds__(256) void fc_kernel(
    const float* __restrict__ image,
    const float* __restrict__ W0t0, const float* __restrict__ b0t0,
    const float* __restrict__ W1t0, const float* __restrict__ b1t0,
    const float* __restrict__ W2t0, const float* __restrict__ b2t0,
    const float* __restrict__ W0t1, const float* __restrict__ b0t1,
    const float* __restrict__ W1t1, const float* __restrict__ b1t1,
    const float* __restrict__ W2t1, const float* __restrict__ b2t1,
    float* __restrict__ Ei_out)
{
    __shared__ float W0s[NFEAT * W0P];   // padded rows: [f][i]
    __shared__ float W1s[H * W1P];       // padded rows: [i][j]
    __shared__ float W2s[H], b0s[H], b1s[H];
    __shared__ float b2s;
    __shared__ float xs[APB][NFEAT];
    __shared__ float h0s[APB][H];
    __shared__ float g1s[APB][H];
    __shared__ float g0s[APB][H];

    const int tid = threadIdx.x;
    const int w   = tid >> 5;
    const int l   = tid & 31;
    const int atom0 = blockIdx.x * APB + w * APW;
    const int wa    = w * APW;
    const int type  = ((blockIdx.x * APB) & (NATOM - 1)) >= 128 ? 1 : 0;

    const float* W0 = type ? W0t1 : W0t0;
    const float* B0 = type ? b0t1 : b0t0;
    const float* W1 = type ? W1t1 : W1t0;
    const float* B1 = type ? b1t1 : b1t0;
    const float* W2 = type ? W2t1 : W2t0;
    const float* B2 = type ? b2t1 : b2t0;

    // x load first (independent of weight staging; only this warp reads xs[wa..])
    {
        const float* xg = image + (size_t)atom0 * NFEAT;
        for (int i = l; i < APW * NFEAT; i += 32)
            xs[wa + i / NFEAT][i % NFEAT] = xg[i];
    }

    for (int i = tid; i < NFEAT * H; i += 256) W0s[(i / H) * W0P + (i % H)] = W0[i];
    for (int i = tid; i < H * H;     i += 256) W1s[(i / H) * W1P + (i % H)] = W1[i];
    if (tid < H) { W2s[tid] = W2[tid]; b0s[tid] = B0[tid]; b1s[tid] = B1[tid]; }
    if (tid == 0) b2s = B2[0];
    __syncthreads();

    const bool hi = (l < H - 32);   // l < 18 handles output index l+32

    // ---- layer 0: h0 = tanh(x @ W0 + b0) ----
    float h0A[APW], h0B[APW];
    #pragma unroll
    for (int a = 0; a < APW; ++a) { h0A[a] = b0s[l]; h0B[a] = hi ? b0s[l + 32] : 0.f; }
    #pragma unroll
    for (int f = 0; f < NFEAT; ++f) {
        float wlo = W0s[f * W0P + l];
        float whi = hi ? W0s[f * W0P + l + 32] : 0.f;
        #pragma unroll
        for (int a = 0; a < APW; ++a) {
            float xv = xs[wa + a][f];
            h0A[a] = fmaf(wlo, xv, h0A[a]);
            h0B[a] = fmaf(whi, xv, h0B[a]);
        }
    }
    #pragma unroll
    for (int a = 0; a < APW; ++a) {
        h0A[a] = tanh_fast(h0A[a]);
        h0s[wa + a][l] = h0A[a];
        if (hi) { h0B[a] = tanh_fast(h0B[a]); h0s[wa + a][l + 32] = h0B[a]; }
    }
    __syncwarp();

    // ---- layer 1: h1 = tanh(h0 @ W1 + b1) ----
    float h1A[APW], h1B[APW];
    #pragma unroll
    for (int a = 0; a < APW; ++a) { h1A[a] = b1s[l]; h1B[a] = hi ? b1s[l + 32] : 0.f; }
    #pragma unroll
    for (int i = 0; i < H; ++i) {
        float wlo = W1s[i * W1P + l];
        float whi = hi ? W1s[i * W1P + l + 32] : 0.f;
        #pragma unroll
        for (int a = 0; a < APW; ++a) {
            float hv = h0s[wa + a][i];
            h1A[a] = fmaf(wlo, hv, h1A[a]);
            h1B[a] = fmaf(whi, hv, h1B[a]);
        }
    }
    #pragma unroll
    for (int a = 0; a < APW; ++a) {
        h1A[a] = tanh_fast(h1A[a]);
        if (hi) h1B[a] = tanh_fast(h1B[a]);
    }

    // ---- Ei = h1 @ W2 + b2 ----
    #pragma unroll
    for (int a = 0; a < APW; ++a) {
        float p = h1A[a] * W2s[l] + (hi ? h1B[a] * W2s[l + 32] : 0.f);
        #pragma unroll
        for (int off = 16; off > 0; off >>= 1)
            p += __shfl_down_sync(0xFFFFFFFFu, p, off);
        if (l == 0) Ei_out[atom0 + a] = p + b2s;
    }

    // ---- backward: g1 = W2 * (1 - h1^2) ----
    #pragma unroll
    for (int a = 0; a < APW; ++a) {
        g1s[wa + a][l] = W2s[l] * (1.f - h1A[a] * h1A[a]);
        if (hi) g1s[wa + a][l + 32] = W2s[l + 32] * (1.f - h1B[a] * h1B[a]);
    }
    __syncwarp();

    // ---- g0[i] = (sum_j W1[i,j] * g1[j]) * (1 - h0[i]^2) ----
    float gA[APW], gB[APW];
    #pragma unroll
    for (int a = 0; a < APW; ++a) { gA[a] = 0.f; gB[a] = 0.f; }
    #pragma unroll
    for (int j = 0; j < H; ++j) {
        float wlo = W1s[l * W1P + j];
        float whi = hi ? W1s[(l + 32) * W1P + j] : 0.f;
        #pragma unroll
        for (int a = 0; a < APW; ++a) {
            float gv = g1s[wa + a][j];
            gA[a] = fmaf(wlo, gv, gA[a]);
            gB[a] = fmaf(whi, gv, gB[a]);
        }
    }
    #pragma unroll
    for (int a = 0; a < APW; ++a) {
        gA[a] *= (1.f - h0A[a] * h0A[a]);
        g0s[wa + a][l] = gA[a];
        if (hi) { gB[a] *= (1.f - h0B[a] * h0B[a]); g0s[wa + a][l + 32] = gB[a]; }
    }
    __syncwarp();

    // ---- dx[f] = sum_i W0[f,i] * g0[i] ----
    const bool lo2 = (l < NFEAT - 32);  // l < 10
    float dA[APW], dB[APW];
    #pragma unroll
    for (int a = 0; a < APW; ++a) { dA[a] = 0.f; dB[a] = 0.f; }
    #pragma unroll
    for (int i = 0; i < H; ++i) {
        float wlo = W0s[l * W0P + i];
        float whi = lo2 ? W0s[(l + 32) * W0P + i] : 0.f;
        #pragma unroll
        for (int a = 0; a < APW; ++a) {
            float gv = g0s[wa + a][i];
            dA[a] = fmaf(wlo, gv, dA[a]);
            dB[a] = fmaf(whi, gv, dB[a]);
        }
    }
    #pragma unroll
    for (int a = 0; a < APW; ++a) {
        float* dE = g_dE + (size_t)(atom0 + a) * DE_PAD;
        dE[l] = dA[a];
        if (lo2) dE[l + 32] = dB[a];
    }
}

// ---------------------------------------------------------------------------
// Kernel B: Etot[b] = sum_n Ei[b, n]. One block per batch.
// ---------------------------------------------------------------------------
__global__ __launch_bounds__(256) void etot_kernel(
    const float* __restrict__ Ei, float* __restrict__ Etot)
{
    __shared__ float s[256];
    int b = blockIdx.x, tid = threadIdx.x;
    s[tid] = Ei[b * NATOM + tid];
    __syncthreads();
    for (int off = 128; off > 0; off >>= 1) {
        if (tid < off) s[tid] += s[tid + off];
        __syncthreads();
    }
    if (tid == 0) Etot[b] = s[0];
}

// ---------------------------------------------------------------------------
// Kernel C (unchanged from R11 — 61us, ~90% of DRAM floor).
// ---------------------------------------------------------------------------
__global__ __launch_bounds__(256) void force_kernel(
    const float* __restrict__ dfeat,
    const int* __restrict__ neighbor,
    float* __restrict__ force)
{
    __shared__ int    nbr[NN];
    __shared__ float  dEs[NN * DE_PAD];   // 100 x 48 floats = 19.2 KB
    __shared__ float  red[3][256];        // 3 KB

    const int tid  = threadIdx.x;
    const int atom = blockIdx.x;
    const int b    = atom >> 8;

    const int* nb = neighbor + (size_t)atom * NN;
    if (tid < NN) nbr[tid] = nb[tid];
    __syncthreads();

    // gather neighbor dE rows as float4 (12 per row); neighbor==0 -> zero row
    {
        const float4* gdE4 = (const float4*)g_dE;
        float4* dEs4 = (float4*)dEs;
        const float4 z4 = make_float4(0.f, 0.f, 0.f, 0.f);
        #pragma unroll
        for (int it = 0; it < 5; ++it) {            // 5*256 = 1280 >= 1200
            int idx = tid + it * 256;
            if (idx < NN * (DE_PAD / 4)) {
                int k = idx / (DE_PAD / 4);
                int q = idx - k * (DE_PAD / 4);
                int v = nbr[k];
                dEs4[idx] = v ? gdE4[(size_t)(b * NATOM + v - 1) * (DE_PAD / 4) + q] : z4;
            }
        }
    }
    __syncthreads();

    // loop-invariant element mapping: 2-row chunk = 252 floats = 63 float4
    const int g  = tid >> 6;        // group 0..3 -> row-pair offset 2g
    const int tt = tid & 63;        // float4 slot within chunk
    const bool act = (tt < 63);

    int koff[4], ff[4];
    #pragma unroll
    for (int j = 0; j < 4; ++j) {
        int e = 4 * tt + j;             // element in [0, 252)
        koff[j] = e / 126;
        int r = e - 126 * koff[j];
        ff[j] = r / 3;
    }
    const int d0 = (4 * tt) % 3;        // d of elements j=0 and j=3

    const float4* df4 = (const float4*)(dfeat + (size_t)atom * DF_PER_ATOM);
    float acc0 = 0.f, acc1 = 0.f, acc2 = 0.f, acc3 = 0.f;

    // software-pipelined stream: prefetch next chunk while consuming current
    float4 v = make_float4(0.f, 0.f, 0.f, 0.f);
    {
        int krow = 2 * g;
        if (act && krow < NN) v = __ldcs(df4 + (size_t)(krow >> 1) * 63 + tt);
    }
    #pragma unroll
    for (int kb = 0; kb < NN; kb += 8) {
        const int krow  = kb + 2 * g;
        const int krown = krow + 8;
        float4 vn = make_float4(0.f, 0.f, 0.f, 0.f);
        if (act && krown < NN) vn = __ldcs(df4 + (size_t)(krown >> 1) * 63 + tt);
        if (act && krow < NN) {
            acc0 = fmaf(dEs[(krow + koff[0]) * DE_PAD + ff[0]], v.x, acc0);
            acc1 = fmaf(dEs[(krow + koff[1]) * DE_PAD + ff[1]], v.y, acc1);
            acc2 = fmaf(dEs[(krow + koff[2]) * DE_PAD + ff[2]], v.z, acc2);
            acc3 = fmaf(dEs[(krow + koff[3]) * DE_PAD + ff[3]], v.w, acc3);
        }
        v = vn;
    }

    // deposit per-d partials (d of j: d0, d0+1, d0+2, d0)
    if (act) {
        red[d0][tid]           = acc0 + acc3;
        red[(d0 + 1) % 3][tid] = acc1;
        red[(d0 + 2) % 3][tid] = acc2;
    } else {
        red[0][tid] = 0.f; red[1][tid] = 0.f; red[2][tid] = 0.f;
    }
    __syncthreads();

    if (tid < 96) {
        const int d = tid >> 5, ln = tid & 31;
        float s = 0.f;
        #pragma unroll
        for (int c = 0; c < 256; c += 32) s += red[d][ln + c];
        #pragma unroll
        for (int off = 16; off > 0; off >>= 1)
            s += __shfl_down_sync(0xFFFFFFFFu, s, off);
        if (ln == 0) force[(size_t)atom * 3 + d] = s;
    }
}

// ---------------------------------------------------------------------------
// Launch. Output layout (fp32): [Etot(32) | Ei(8192) | Force(24576)] = 32800
// ---------------------------------------------------------------------------
extern "C" void kernel_launch(void* const* d_in, const int* in_sizes, int n_in,
                              void* d_out, int out_size)
{
    const float* image    = (const float*)d_in[0];
    const float* dfeat    = (const float*)d_in[1];
    const int*   neighbor = (const int*)d_in[2];
    const float *W0t0 = (const float*)d_in[3],  *b0t0 = (const float*)d_in[4];
    const float *W1t0 = (const float*)d_in[5],  *b1t0 = (const float*)d_in[6];
    const float *W2t0 = (const float*)d_in[7],  *b2t0 = (const float*)d_in[8];
    const float *W0t1 = (const float*)d_in[9],  *b0t1 = (const float*)d_in[10];
    const float *W1t1 = (const float*)d_in[11], *b1t1 = (const float*)d_in[12];
    const float *W2t1 = (const float*)d_in[13], *b2t1 = (const float*)d_in[14];

    float* out    = (float*)d_out;
    float* etot   = out;
    float* ei     = out + BATCH;
    float* forceo = out + BATCH + NATOMS;

    fc_kernel<<<NATOMS / APB, 256>>>(image,
        W0t0, b0t0, W1t0, b1t0, W2t0, b2t0,
        W0t1, b0t1, W1t1, b1t1, W2t1, b2t1,
        ei);
    etot_kernel<<<BATCH, 256>>>(ei, etot);
    force_kernel<<<NATOMS, 256>>>(dfeat, neighbor, forceo);
}